// round 2
// baseline (speedup 1.0000x reference)
#include <cuda_runtime.h>

#define NN 50000
#define NE 800000
#define D  128
#define NBLK 98            // ceil(50000/512)

// ---- scratch (no allocations allowed) ----
__device__ int   g_src[NE];
__device__ int   g_dst[NE];
__device__ int   g_deg[NN];
__device__ int   g_rowptr[NN + 1];
__device__ int   g_cursor[NN];
__device__ int   g_csr[NE];     // source node per CSR slot (grouped by dst)
__device__ float g_csw[NE];     // dis[src] per CSR slot
__device__ float g_dis[NN];
__device__ float g_h[NN * D];   // GEMM output (both layers)
__device__ float g_x1[NN * D];  // layer-1 activation
__device__ int   g_bsum[128];
__device__ int   g_is64;

// Detect int64 vs int32 edge_index: int64 node ids < 2^31 have zero high words.
__global__ void k_detect(const int* __restrict__ ei32) {
    if (threadIdx.x == 0 && blockIdx.x == 0) {
        int acc = 0;
        for (int i = 1; i < 512; i += 2) acc |= ei32[i];
        g_is64 = (acc == 0) ? 1 : 0;
    }
}

__global__ void k_zero_deg() {
    int i = blockIdx.x * blockDim.x + threadIdx.x;
    if (i < NN) g_deg[i] = 0;
}

__global__ void k_prep(const void* __restrict__ eiv) {
    int e = blockIdx.x * blockDim.x + threadIdx.x;
    if (e >= NE) return;
    int s, d;
    if (g_is64) {
        const long long* ei = (const long long*)eiv;
        s = (int)ei[e];
        d = (int)ei[NE + e];
    } else {
        const int* ei = (const int*)eiv;
        s = ei[e];
        d = ei[NE + e];
    }
    // defensive clamp: never trap on bad data
    if ((unsigned)s >= NN) s = 0;
    if ((unsigned)d >= NN) d = 0;
    g_src[e] = s;
    g_dst[e] = d;
    atomicAdd(&g_deg[d], 1);
}

__global__ void k_dis() {
    int i = blockIdx.x * blockDim.x + threadIdx.x;
    if (i < NN) g_dis[i] = rsqrtf((float)(g_deg[i] + 1));
}

__global__ void k_partsum() {
    __shared__ int sh[512];
    int t = threadIdx.x;
    int i = blockIdx.x * 512 + t;
    sh[t] = (i < NN) ? g_deg[i] : 0;
    __syncthreads();
    for (int o = 256; o > 0; o >>= 1) {
        if (t < o) sh[t] += sh[t + o];
        __syncthreads();
    }
    if (t == 0) g_bsum[blockIdx.x] = sh[0];
}

__global__ void k_scanb() {  // 1 block, 128 threads: exclusive scan of NBLK block sums
    __shared__ int sh[128];
    int t = threadIdx.x;
    int v = (t < NBLK) ? g_bsum[t] : 0;
    sh[t] = v;
    __syncthreads();
    for (int o = 1; o < 128; o <<= 1) {
        int a = (t >= o) ? sh[t - o] : 0;
        __syncthreads();
        sh[t] += a;
        __syncthreads();
    }
    if (t < NBLK) g_bsum[t] = sh[t] - v;   // exclusive
}

__global__ void k_rowptr() {
    __shared__ int sh[512];
    int t = threadIdx.x;
    int i = blockIdx.x * 512 + t;
    int v = (i < NN) ? g_deg[i] : 0;
    sh[t] = v;
    __syncthreads();
    for (int o = 1; o < 512; o <<= 1) {
        int a = (t >= o) ? sh[t - o] : 0;
        __syncthreads();
        sh[t] += a;
        __syncthreads();
    }
    if (i < NN) {
        int ex = g_bsum[blockIdx.x] + sh[t] - v;
        g_rowptr[i] = ex;
        g_cursor[i] = ex;
    }
    if (i == 0) g_rowptr[NN] = NE;
}

__global__ void k_fill() {
    int e = blockIdx.x * blockDim.x + threadIdx.x;
    if (e >= NE) return;
    int d = g_dst[e];
    int s = g_src[e];
    int pos = atomicAdd(&g_cursor[d], 1);
    if ((unsigned)pos < NE) {
        g_csr[pos] = s;
        g_csw[pos] = g_dis[s];
    }
}

// GEMM: out(g_h)[NN,128] = x[NN,128] @ W[128,128]
// block: 256 threads, 8 warps; block tile = 32 rows; each warp: 4 rows,
// each lane: 4 contiguous columns (float4).
__global__ void k_gemm(const float* __restrict__ x_ext, const float* __restrict__ W,
                       int use_x1) {
    const float* x = use_x1 ? g_x1 : x_ext;
    __shared__ float xs[32 * 128];
    int t    = threadIdx.x;
    int base = blockIdx.x * 32;

    const float4* x4  = (const float4*)x;
    float4*       xs4 = (float4*)xs;
    for (int i = t; i < 32 * 32; i += 256) {
        int r = i >> 5, c = i & 31;
        int g = base + r;
        float4 v = make_float4(0.f, 0.f, 0.f, 0.f);
        if (g < NN) v = x4[g * 32 + c];
        xs4[i] = v;
    }
    __syncthreads();

    int w = t >> 5, lane = t & 31;
    int r0 = w * 4;
    const float4* W4 = (const float4*)W;

    float4 acc[4];
#pragma unroll
    for (int r = 0; r < 4; r++) acc[r] = make_float4(0.f, 0.f, 0.f, 0.f);

    for (int k0 = 0; k0 < 128; k0 += 4) {
        float xa[4][4];
#pragma unroll
        for (int r = 0; r < 4; r++) {
            float4 xv = *(const float4*)&xs[(r0 + r) * 128 + k0];
            xa[r][0] = xv.x; xa[r][1] = xv.y; xa[r][2] = xv.z; xa[r][3] = xv.w;
        }
#pragma unroll
        for (int kk = 0; kk < 4; kk++) {
            float4 wv = W4[(k0 + kk) * 32 + lane];
#pragma unroll
            for (int r = 0; r < 4; r++) {
                acc[r].x = fmaf(xa[r][kk], wv.x, acc[r].x);
                acc[r].y = fmaf(xa[r][kk], wv.y, acc[r].y);
                acc[r].z = fmaf(xa[r][kk], wv.z, acc[r].z);
                acc[r].w = fmaf(xa[r][kk], wv.w, acc[r].w);
            }
        }
    }

    float4* out4 = (float4*)g_h;
#pragma unroll
    for (int r = 0; r < 4; r++) {
        int g = base + r0 + r;
        if (g < NN) out4[g * 32 + lane] = acc[r];
    }
}

// Aggregation: one warp per node, lane holds 4 contiguous columns (float4).
// out[d] = dis[d] * sum_e( dis[src_e] * h[src_e] ) + dis[d]^2 * h[d] + bias
__global__ void k_agg(const float* __restrict__ bias, float* __restrict__ out_ext,
                      int layer) {
    int node = blockIdx.x * (blockDim.x >> 5) + (threadIdx.x >> 5);
    if (node >= NN) return;
    int lane = threadIdx.x & 31;

    int beg = g_rowptr[node];
    int end = g_rowptr[node + 1];

    const float4* h4 = (const float4*)g_h;
    float4 acc = make_float4(0.f, 0.f, 0.f, 0.f);

    for (int e = beg; e < end; e++) {
        int   s = g_csr[e];
        float c = g_csw[e];
        float4 v = h4[s * 32 + lane];
        acc.x = fmaf(c, v.x, acc.x);
        acc.y = fmaf(c, v.y, acc.y);
        acc.z = fmaf(c, v.z, acc.z);
        acc.w = fmaf(c, v.w, acc.w);
    }

    float dn = g_dis[node];
    float sn = dn * dn;
    float4 hv = h4[node * 32 + lane];
    float4 b  = ((const float4*)bias)[lane];

    float4 r;
    r.x = dn * acc.x + sn * hv.x + b.x;
    r.y = dn * acc.y + sn * hv.y + b.y;
    r.z = dn * acc.z + sn * hv.z + b.z;
    r.w = dn * acc.w + sn * hv.w + b.w;

    if (layer == 0) {
        r.x = fmaxf(r.x, 0.f);
        r.y = fmaxf(r.y, 0.f);
        r.z = fmaxf(r.z, 0.f);
        r.w = fmaxf(r.w, 0.f);
        ((float4*)g_x1)[node * 32 + lane] = r;
    } else {
        ((float4*)out_ext)[node * 32 + lane] = r;
    }
}

extern "C" void kernel_launch(void* const* d_in, const int* in_sizes, int n_in,
                              void* d_out, int out_size) {
    const void*  ei  = d_in[0];
    const float* emb = (const float*)d_in[1];
    const float* W1  = (const float*)d_in[2];
    const float* b1  = (const float*)d_in[3];
    const float* W2  = (const float*)d_in[4];
    const float* b2  = (const float*)d_in[5];
    float* out = (float*)d_out;

    (void)in_sizes; (void)n_in; (void)out_size;

    // ---- graph preprocessing (per launch; edge set is an input) ----
    k_detect<<<1, 32>>>((const int*)ei);
    k_zero_deg<<<(NN + 255) / 256, 256>>>();
    k_prep<<<(NE + 255) / 256, 256>>>(ei);
    k_dis<<<(NN + 255) / 256, 256>>>();
    k_partsum<<<NBLK, 512>>>();
    k_scanb<<<1, 128>>>();
    k_rowptr<<<NBLK, 512>>>();
    k_fill<<<(NE + 255) / 256, 256>>>();

    // ---- layer 1 ----
    k_gemm<<<(NN + 31) / 32, 256>>>(emb, W1, 0);
    k_agg<<<(NN + 7) / 8, 256>>>(b1, out, 0);   // writes g_x1 (relu)

    // ---- layer 2 ----
    k_gemm<<<(NN + 31) / 32, 256>>>(nullptr, W2, 1);
    k_agg<<<(NN + 7) / 8, 256>>>(b2, out, 1);   // writes d_out
}